// round 7
// baseline (speedup 1.0000x reference)
#include <cuda_runtime.h>
#include <cuda_fp16.h>

#define NN 100000
#define EMAX 800000
#define NBLK ((NN + 255) / 256)  // 391

// ---------------- device scratch (no allocations allowed) ----------------
__device__ __align__(16) __half2 g_hs16[NN * 32];   // h1*dinv fp16 [N,64] (128B/row)
__device__ __align__(16) float4 g_agg[NN * 16];     // layer1 aggregate fp32
__device__ __align__(16) __half2 g_h2s16[NN * 8];   // h2*dinv fp16 [N,16] (32B/row)
__device__ unsigned g_deg[NN];       // zero at start of each call (agg2 resets)
__device__ unsigned g_rowstart[NN];
__device__ unsigned g_cursor[NN];
__device__ unsigned g_blocksum[NBLK];
__device__ unsigned g_blockoff[NBLK];
__device__ int g_csr[EMAX];          // source ids grouped by target
__device__ float g_dinv[NN];

// int64-vs-int32 detection (full-warp). Little-endian int64 with ids<100000
// => every odd int32 slot is 0; for int32 those slots are random ids.
__device__ __forceinline__ bool detect64(const int* __restrict__ e32) {
    int v = __ldg(&e32[2 * (threadIdx.x & 31) + 1]);
    return __ballot_sync(0xffffffffu, v != 0) == 0u;
}
__device__ __forceinline__ int load_idx(const int* __restrict__ e32, int i, bool is64) {
    return __ldg(&e32[is64 ? 2 * (long long)i : (long long)i]);
}
__device__ __forceinline__ int load_idx2(const int* __restrict__ e32, int E, int i,
                                         bool is64) {
    return __ldg(&e32[is64 ? 2 * ((long long)E + i) : (long long)(E + i)]);
}

// ---------------- degree histogram ----------------
__global__ void deg_count_kernel(const int* __restrict__ e32, int E) {
    bool is64 = detect64(e32);
    int t = blockIdx.x * blockDim.x + threadIdx.x;
    if (t >= E) return;
    atomicAdd(&g_deg[load_idx2(e32, E, t, is64)], 1u);
}

// ---------------- 3-kernel exclusive scan of g_deg -> g_rowstart ----------
__global__ void scan1_kernel() {
    int tid = threadIdx.x;
    int i = blockIdx.x * 256 + tid;
    unsigned v = (i < NN) ? g_deg[i] : 0u;
#pragma unroll
    for (int d = 16; d; d >>= 1) v += __shfl_xor_sync(0xffffffffu, v, d);
    __shared__ unsigned wt[8];
    if ((tid & 31) == 0) wt[tid >> 5] = v;
    __syncthreads();
    if (tid == 0) {
        unsigned s = 0;
#pragma unroll
        for (int w = 0; w < 8; w++) s += wt[w];
        g_blocksum[blockIdx.x] = s;
    }
}

__global__ void scan2_kernel() {  // single block, 512 threads; NBLK <= 512
    __shared__ unsigned s[512];
    int tid = threadIdx.x;
    unsigned v = (tid < NBLK) ? g_blocksum[tid] : 0u;
    s[tid] = v;
    __syncthreads();
    for (int d = 1; d < 512; d <<= 1) {
        unsigned t2 = (tid >= d) ? s[tid - d] : 0u;
        __syncthreads();
        s[tid] += t2;
        __syncthreads();
    }
    if (tid < NBLK) g_blockoff[tid] = s[tid] - v;  // exclusive
}

__global__ void scan3_kernel() {
    int tid = threadIdx.x, lane = tid & 31, wid = tid >> 5;
    int i = blockIdx.x * 256 + tid;
    unsigned v = (i < NN) ? g_deg[i] : 0u;
    unsigned s = v;
#pragma unroll
    for (int d = 1; d < 32; d <<= 1) {
        unsigned n = __shfl_up_sync(0xffffffffu, s, d);
        if (lane >= d) s += n;
    }
    __shared__ unsigned wt[8];
    if (lane == 31) wt[wid] = s;
    __syncthreads();
    if (tid < 8) {
        unsigned w = wt[tid], ws = w;
#pragma unroll
        for (int d = 1; d < 8; d <<= 1) {
            unsigned n = __shfl_up_sync(0xffu, ws, d);
            if (tid >= d) ws += n;
        }
        wt[tid] = ws - w;
    }
    __syncthreads();
    unsigned excl = s - v + wt[wid] + g_blockoff[blockIdx.x];
    if (i < NN) {
        g_rowstart[i] = excl;
        g_cursor[i] = excl;
    }
}

// ---------------- CSR fill ----------------
__global__ void csr_fill_kernel(const int* __restrict__ e32, int E) {
    bool is64 = detect64(e32);
    int t = blockIdx.x * blockDim.x + threadIdx.x;
    if (t >= E) return;
    int r = load_idx(e32, t, is64);
    int c = load_idx2(e32, E, t, is64);
    unsigned pos = atomicAdd(&g_cursor[c], 1u);
    g_csr[pos] = r;
}

// ---------------- small GEMM helpers ----------------
template <int NJ>
__device__ __forceinline__ void fma_row(float4* acc, float xs, const float4* wr) {
#pragma unroll
    for (int j = 0; j < NJ; j++) {
        float4 w = wr[j];
        acc[j].x = fmaf(xs, w.x, acc[j].x);
        acc[j].y = fmaf(xs, w.y, acc[j].y);
        acc[j].z = fmaf(xs, w.z, acc[j].z);
        acc[j].w = fmaf(xs, w.w, acc[j].w);
    }
}

// mm1: 2 threads/row; dinv = rsqrt(deg+1); hs16 = (x@W1)*dinv (fp16 only).
__global__ void __launch_bounds__(256) mm1_kernel(const float4* __restrict__ X4,
                                                  const float* __restrict__ W) {
    __shared__ float4 sW[64 * 16];
    for (int i = threadIdx.x; i < 64 * 16; i += 256) sW[i] = ((const float4*)W)[i];
    __syncthreads();
    int t = blockIdx.x * 256 + threadIdx.x;
    int row = t >> 1;
    int half = t & 1;
    if (row >= NN) return;
    float dv = rsqrtf((float)(g_deg[row] + 1u));
    if (half == 0) g_dinv[row] = dv;
    float4 acc[8];
#pragma unroll
    for (int j = 0; j < 8; j++) acc[j] = make_float4(0.f, 0.f, 0.f, 0.f);
    const float4* wbase = &sW[half * 8];
#pragma unroll 4
    for (int k4 = 0; k4 < 16; k4++) {
        float4 xv = __ldg(&X4[(long long)row * 16 + k4]);
        fma_row<8>(acc, xv.x, wbase + (k4 * 4 + 0) * 16);
        fma_row<8>(acc, xv.y, wbase + (k4 * 4 + 1) * 16);
        fma_row<8>(acc, xv.z, wbase + (k4 * 4 + 2) * 16);
        fma_row<8>(acc, xv.w, wbase + (k4 * 4 + 3) * 16);
    }
    union { __half2 h[4]; uint4 u; } pk;
#pragma unroll
    for (int j = 0; j < 8; j++) {
        float4 v = make_float4(acc[j].x * dv, acc[j].y * dv, acc[j].z * dv, acc[j].w * dv);
        pk.h[(j & 1) * 2 + 0] = __floats2half2_rn(v.x, v.y);
        pk.h[(j & 1) * 2 + 1] = __floats2half2_rn(v.z, v.w);
        if (j & 1) *(uint4*)&g_hs16[row * 32 + half * 16 + (j - 1) * 2] = pk.u;
    }
}

// ---------------- layer1 aggregate: warp per node, NO atomics ----------
// 16 lanes per feature-slice, 2 neighbors in flight (sub = lane>>4).
__global__ void __launch_bounds__(256) agg1_kernel() {
    int node = blockIdx.x * 8 + (threadIdx.x >> 5);
    if (node >= NN) return;
    int lane = threadIdx.x & 31;
    int q = lane & 15, sub = lane >> 4;
    unsigned start = g_rowstart[node];
    unsigned cnt = g_deg[node];
    float4 acc = make_float4(0.f, 0.f, 0.f, 0.f);
    for (unsigned e = sub; e < cnt; e += 2) {
        int r = __ldg(&g_csr[start + e]);
        uint2 u = __ldg((const uint2*)&g_hs16[r * 32 + 2 * q]);
        float2 f0 = __half22float2(*(__half2*)&u.x);
        float2 f1 = __half22float2(*(__half2*)&u.y);
        acc.x += f0.x; acc.y += f0.y; acc.z += f1.x; acc.w += f1.y;
    }
    acc.x += __shfl_xor_sync(0xffffffffu, acc.x, 16);
    acc.y += __shfl_xor_sync(0xffffffffu, acc.y, 16);
    acc.z += __shfl_xor_sync(0xffffffffu, acc.z, 16);
    acc.w += __shfl_xor_sync(0xffffffffu, acc.w, 16);
    if (sub == 0) {  // add self-loop message, single coalesced write
        uint2 u = __ldg((const uint2*)&g_hs16[node * 32 + 2 * q]);
        float2 f0 = __half22float2(*(__half2*)&u.x);
        float2 f1 = __half22float2(*(__half2*)&u.y);
        g_agg[node * 16 + q] =
            make_float4(acc.x + f0.x, acc.y + f0.y, acc.z + f1.x, acc.w + f1.y);
    }
}

// mm2: 2 threads/row; a = relu(agg*dinv + b1); h2s16 = (a@W2)*dinv.
__global__ void __launch_bounds__(256) mm2_kernel(const float* __restrict__ W2,
                                                  const float* __restrict__ b1) {
    __shared__ float4 sW[64 * 4];
    __shared__ float4 sB1[16];
    for (int i = threadIdx.x; i < 64 * 4; i += 256) sW[i] = ((const float4*)W2)[i];
    if (threadIdx.x < 16) sB1[threadIdx.x] = ((const float4*)b1)[threadIdx.x];
    __syncthreads();
    int t = blockIdx.x * 256 + threadIdx.x;
    int row = t >> 1;
    int half = t & 1;
    if (row >= NN) return;
    float dv = g_dinv[row];
    float4 acc[2];
    acc[0] = make_float4(0.f, 0.f, 0.f, 0.f);
    acc[1] = make_float4(0.f, 0.f, 0.f, 0.f);
    const float4* wbase = &sW[half * 2];
#pragma unroll 4
    for (int k4 = 0; k4 < 16; k4++) {
        float4 a = g_agg[row * 16 + k4];
        float4 bb = sB1[k4];
        a.x = fmaxf(fmaf(a.x, dv, bb.x), 0.f);
        a.y = fmaxf(fmaf(a.y, dv, bb.y), 0.f);
        a.z = fmaxf(fmaf(a.z, dv, bb.z), 0.f);
        a.w = fmaxf(fmaf(a.w, dv, bb.w), 0.f);
        fma_row<2>(acc, a.x, wbase + (k4 * 4 + 0) * 4);
        fma_row<2>(acc, a.y, wbase + (k4 * 4 + 1) * 4);
        fma_row<2>(acc, a.z, wbase + (k4 * 4 + 2) * 4);
        fma_row<2>(acc, a.w, wbase + (k4 * 4 + 3) * 4);
    }
    union { __half2 h[4]; uint4 u; } pk;
#pragma unroll
    for (int j = 0; j < 2; j++) {
        float4 v = make_float4(acc[j].x * dv, acc[j].y * dv, acc[j].z * dv, acc[j].w * dv);
        pk.h[j * 2 + 0] = __floats2half2_rn(v.x, v.y);
        pk.h[j * 2 + 1] = __floats2half2_rn(v.z, v.w);
    }
    *(uint4*)&g_h2s16[row * 8 + half * 4] = pk.u;
}

// ---------------- layer2 aggregate + finalize: warp per node -------------
// 4 lanes per feature-slice, 8 neighbors in flight; writes d_out directly.
__global__ void __launch_bounds__(256) agg2_kernel(const float4* __restrict__ b2,
                                                   float4* __restrict__ out4) {
    int node = blockIdx.x * 8 + (threadIdx.x >> 5);
    if (node >= NN) return;
    int lane = threadIdx.x & 31;
    int q = lane & 3, sub = lane >> 2;
    unsigned start = g_rowstart[node];
    unsigned cnt = g_deg[node];
    float4 acc = make_float4(0.f, 0.f, 0.f, 0.f);
    for (unsigned e = sub; e < cnt; e += 8) {
        int r = __ldg(&g_csr[start + e]);
        uint2 u = __ldg((const uint2*)&g_h2s16[r * 8 + 2 * q]);
        float2 f0 = __half22float2(*(__half2*)&u.x);
        float2 f1 = __half22float2(*(__half2*)&u.y);
        acc.x += f0.x; acc.y += f0.y; acc.z += f1.x; acc.w += f1.y;
    }
#pragma unroll
    for (int d = 4; d < 32; d <<= 1) {
        acc.x += __shfl_xor_sync(0xffffffffu, acc.x, d);
        acc.y += __shfl_xor_sync(0xffffffffu, acc.y, d);
        acc.z += __shfl_xor_sync(0xffffffffu, acc.z, d);
        acc.w += __shfl_xor_sync(0xffffffffu, acc.w, d);
    }
    if (lane == 0) g_deg[node] = 0u;  // reset for next replay
    if (sub == 0) {
        uint2 u = __ldg((const uint2*)&g_h2s16[node * 8 + 2 * q]);
        float2 f0 = __half22float2(*(__half2*)&u.x);
        float2 f1 = __half22float2(*(__half2*)&u.y);
        float dv = __ldg(&g_dinv[node]);
        float4 bv = __ldg(&b2[q]);
        out4[node * 4 + q] =
            make_float4(fmaf(acc.x + f0.x, dv, bv.x), fmaf(acc.y + f0.y, dv, bv.y),
                        fmaf(acc.z + f1.x, dv, bv.z), fmaf(acc.w + f1.y, dv, bv.w));
    }
}

// ---------------- launch ----------------
extern "C" void kernel_launch(void* const* d_in, const int* in_sizes, int n_in,
                              void* d_out, int out_size) {
    const float* x = (const float*)d_in[0];
    const int* e32 = (const int*)d_in[1];
    const float* W1 = (const float*)d_in[2];
    const float* b1 = (const float*)d_in[3];
    const float* W2 = (const float*)d_in[4];
    const float* b2 = (const float*)d_in[5];
    int E = in_sizes[1] / 2;
    if (E > EMAX) E = EMAX;

    deg_count_kernel<<<(E + 255) / 256, 256>>>(e32, E);
    scan1_kernel<<<NBLK, 256>>>();
    scan2_kernel<<<1, 512>>>();
    scan3_kernel<<<NBLK, 256>>>();
    csr_fill_kernel<<<(E + 255) / 256, 256>>>(e32, E);
    mm1_kernel<<<(NN * 2 + 255) / 256, 256>>>((const float4*)x, W1);
    agg1_kernel<<<(NN + 7) / 8, 256>>>();
    mm2_kernel<<<(NN * 2 + 255) / 256, 256>>>(W2, b1);
    agg2_kernel<<<(NN + 7) / 8, 256>>>((const float4*)b2, (float4*)d_out);
}

// round 8
// speedup vs baseline: 1.0133x; 1.0133x over previous
#include <cuda_runtime.h>
#include <cuda_fp16.h>

#define NN 100000
#define EMAX 800000
#define NBLK ((NN + 255) / 256)  // 391

// ---------------- device scratch (no allocations allowed) ----------------
__device__ __align__(16) __half2 g_hs16[NN * 32];   // h1*dinv fp16 [N,64] (128B/row)
__device__ __align__(16) float4 g_agg[NN * 16];     // layer1 aggregate fp32
__device__ __align__(16) __half2 g_h2s16[NN * 8];   // h2*dinv fp16 [N,16] (32B/row)
__device__ unsigned g_deg[NN];       // zero at call start (agg2 resets)
__device__ unsigned g_rowstart[NN];
__device__ unsigned g_cursor[NN];
__device__ unsigned g_total;         // zero at call start (agg2 resets)
__device__ int g_csr[EMAX];          // source ids grouped by target
__device__ float g_dinv[NN];

// int64-vs-int32 detection (full-warp). Little-endian int64 with ids<100000
// => every odd int32 slot is 0; for int32 those slots are random ids.
__device__ __forceinline__ bool detect64(const int* __restrict__ e32) {
    int v = __ldg(&e32[2 * (threadIdx.x & 31) + 1]);
    return __ballot_sync(0xffffffffu, v != 0) == 0u;
}
__device__ __forceinline__ int load_idx(const int* __restrict__ e32, int i, bool is64) {
    return __ldg(&e32[is64 ? 2 * (long long)i : (long long)i]);
}
__device__ __forceinline__ int load_idx2(const int* __restrict__ e32, int E, int i,
                                         bool is64) {
    return __ldg(&e32[is64 ? 2 * ((long long)E + i) : (long long)(E + i)]);
}

// ---------------- degree histogram ----------------
__global__ void deg_count_kernel(const int* __restrict__ e32, int E) {
    bool is64 = detect64(e32);
    int t = blockIdx.x * blockDim.x + threadIdx.x;
    if (t >= E) return;
    atomicAdd(&g_deg[load_idx2(e32, E, t, is64)], 1u);
}

// ---------------- fused scan: block-local exclusive scan + atomic offset --
// Block offsets come from atomicAdd completion order: ranges are disjoint and
// correct; only CSR segment placement varies (permutes fp32 add order, same
// noise class as atomics).
__global__ void scan_fused_kernel() {
    int tid = threadIdx.x, lane = tid & 31, wid = tid >> 5;
    int i = blockIdx.x * 256 + tid;
    unsigned v = (i < NN) ? g_deg[i] : 0u;
    unsigned s = v;
#pragma unroll
    for (int d = 1; d < 32; d <<= 1) {
        unsigned n = __shfl_up_sync(0xffffffffu, s, d);
        if (lane >= d) s += n;
    }
    __shared__ unsigned wt[8];
    __shared__ unsigned s_off;
    if (lane == 31) wt[wid] = s;
    __syncthreads();
    if (tid < 8) {
        unsigned w = wt[tid], ws = w;
#pragma unroll
        for (int d = 1; d < 8; d <<= 1) {
            unsigned n = __shfl_up_sync(0xffu, ws, d);
            if (tid >= d) ws += n;
        }
        wt[tid] = ws - w;  // exclusive
        if (tid == 7) s_off = atomicAdd(&g_total, ws);  // block total
    }
    __syncthreads();
    if (i < NN) {
        unsigned rs = s - v + wt[wid] + s_off;
        g_rowstart[i] = rs;
        g_cursor[i] = rs;
    }
}

// ---------------- CSR fill ----------------
__global__ void csr_fill_kernel(const int* __restrict__ e32, int E) {
    bool is64 = detect64(e32);
    int t = blockIdx.x * blockDim.x + threadIdx.x;
    if (t >= E) return;
    int r = load_idx(e32, t, is64);
    int c = load_idx2(e32, E, t, is64);
    unsigned pos = atomicAdd(&g_cursor[c], 1u);
    g_csr[pos] = r;
}

// ---------------- small GEMM helpers ----------------
template <int NJ>
__device__ __forceinline__ void fma_row(float4* acc, float xs, const float4* wr) {
#pragma unroll
    for (int j = 0; j < NJ; j++) {
        float4 w = wr[j];
        acc[j].x = fmaf(xs, w.x, acc[j].x);
        acc[j].y = fmaf(xs, w.y, acc[j].y);
        acc[j].z = fmaf(xs, w.z, acc[j].z);
        acc[j].w = fmaf(xs, w.w, acc[j].w);
    }
}

// mm1: 2 threads/row; dinv = rsqrt(deg+1); hs16 = (x@W1)*dinv (fp16 only).
__global__ void __launch_bounds__(256) mm1_kernel(const float4* __restrict__ X4,
                                                  const float* __restrict__ W) {
    __shared__ float4 sW[64 * 16];
    for (int i = threadIdx.x; i < 64 * 16; i += 256) sW[i] = ((const float4*)W)[i];
    __syncthreads();
    int t = blockIdx.x * 256 + threadIdx.x;
    int row = t >> 1;
    int half = t & 1;
    if (row >= NN) return;
    float dv = rsqrtf((float)(g_deg[row] + 1u));
    if (half == 0) g_dinv[row] = dv;
    float4 acc[8];
#pragma unroll
    for (int j = 0; j < 8; j++) acc[j] = make_float4(0.f, 0.f, 0.f, 0.f);
    const float4* wbase = &sW[half * 8];
#pragma unroll 4
    for (int k4 = 0; k4 < 16; k4++) {
        float4 xv = __ldg(&X4[(long long)row * 16 + k4]);
        fma_row<8>(acc, xv.x, wbase + (k4 * 4 + 0) * 16);
        fma_row<8>(acc, xv.y, wbase + (k4 * 4 + 1) * 16);
        fma_row<8>(acc, xv.z, wbase + (k4 * 4 + 2) * 16);
        fma_row<8>(acc, xv.w, wbase + (k4 * 4 + 3) * 16);
    }
    union { __half2 h[4]; uint4 u; } pk;
#pragma unroll
    for (int j = 0; j < 8; j++) {
        float4 v = make_float4(acc[j].x * dv, acc[j].y * dv, acc[j].z * dv, acc[j].w * dv);
        pk.h[(j & 1) * 2 + 0] = __floats2half2_rn(v.x, v.y);
        pk.h[(j & 1) * 2 + 1] = __floats2half2_rn(v.z, v.w);
        if (j & 1) *(uint4*)&g_hs16[row * 32 + half * 16 + (j - 1) * 2] = pk.u;
    }
}

// ---------------- layer1 aggregate: warp/node, preloaded ids, unrolled ----
__global__ void __launch_bounds__(256) agg1_kernel() {
    int node = blockIdx.x * 8 + (threadIdx.x >> 5);
    if (node >= NN) return;
    int lane = threadIdx.x & 31;
    int q = lane & 15, sub = lane >> 4;
    unsigned start = g_rowstart[node];
    unsigned cnt = g_deg[node];
    float4 acc = make_float4(0.f, 0.f, 0.f, 0.f);
    for (unsigned base = 0; base < cnt; base += 32) {
        unsigned n = cnt - base;
        if (n > 32u) n = 32u;
        // preload up to 32 neighbor ids, one per lane (single coalesced load)
        int id = __ldg(&g_csr[start + base + (lane < n ? lane : n - 1)]);
#pragma unroll 4
        for (unsigned j = 0; j < n; j += 2) {  // n is warp-uniform
            unsigned jj = j + sub;
            int rr = __shfl_sync(0xffffffffu, id, jj < n ? jj : n - 1);
            if (jj < n) {
                uint2 u = __ldg((const uint2*)&g_hs16[rr * 32 + 2 * q]);
                float2 f0 = __half22float2(*(__half2*)&u.x);
                float2 f1 = __half22float2(*(__half2*)&u.y);
                acc.x += f0.x; acc.y += f0.y; acc.z += f1.x; acc.w += f1.y;
            }
        }
    }
    acc.x += __shfl_xor_sync(0xffffffffu, acc.x, 16);
    acc.y += __shfl_xor_sync(0xffffffffu, acc.y, 16);
    acc.z += __shfl_xor_sync(0xffffffffu, acc.z, 16);
    acc.w += __shfl_xor_sync(0xffffffffu, acc.w, 16);
    if (sub == 0) {  // add self-loop message, single coalesced write
        uint2 u = __ldg((const uint2*)&g_hs16[node * 32 + 2 * q]);
        float2 f0 = __half22float2(*(__half2*)&u.x);
        float2 f1 = __half22float2(*(__half2*)&u.y);
        g_agg[node * 16 + q] =
            make_float4(acc.x + f0.x, acc.y + f0.y, acc.z + f1.x, acc.w + f1.y);
    }
}

// mm2: 2 threads/row; a = relu(agg*dinv + b1); h2s16 = (a@W2)*dinv.
__global__ void __launch_bounds__(256) mm2_kernel(const float* __restrict__ W2,
                                                  const float* __restrict__ b1) {
    __shared__ float4 sW[64 * 4];
    __shared__ float4 sB1[16];
    for (int i = threadIdx.x; i < 64 * 4; i += 256) sW[i] = ((const float4*)W2)[i];
    if (threadIdx.x < 16) sB1[threadIdx.x] = ((const float4*)b1)[threadIdx.x];
    __syncthreads();
    int t = blockIdx.x * 256 + threadIdx.x;
    int row = t >> 1;
    int half = t & 1;
    if (row >= NN) return;
    float dv = g_dinv[row];
    float4 acc[2];
    acc[0] = make_float4(0.f, 0.f, 0.f, 0.f);
    acc[1] = make_float4(0.f, 0.f, 0.f, 0.f);
    const float4* wbase = &sW[half * 2];
#pragma unroll 4
    for (int k4 = 0; k4 < 16; k4++) {
        float4 a = g_agg[row * 16 + k4];
        float4 bb = sB1[k4];
        a.x = fmaxf(fmaf(a.x, dv, bb.x), 0.f);
        a.y = fmaxf(fmaf(a.y, dv, bb.y), 0.f);
        a.z = fmaxf(fmaf(a.z, dv, bb.z), 0.f);
        a.w = fmaxf(fmaf(a.w, dv, bb.w), 0.f);
        fma_row<2>(acc, a.x, wbase + (k4 * 4 + 0) * 4);
        fma_row<2>(acc, a.y, wbase + (k4 * 4 + 1) * 4);
        fma_row<2>(acc, a.z, wbase + (k4 * 4 + 2) * 4);
        fma_row<2>(acc, a.w, wbase + (k4 * 4 + 3) * 4);
    }
    union { __half2 h[4]; uint4 u; } pk;
#pragma unroll
    for (int j = 0; j < 2; j++) {
        float4 v = make_float4(acc[j].x * dv, acc[j].y * dv, acc[j].z * dv, acc[j].w * dv);
        pk.h[j * 2 + 0] = __floats2half2_rn(v.x, v.y);
        pk.h[j * 2 + 1] = __floats2half2_rn(v.z, v.w);
    }
    *(uint4*)&g_h2s16[row * 8 + half * 4] = pk.u;
}

// ---------------- layer2 aggregate + finalize: warp/node, 8 nbrs/iter -----
__global__ void __launch_bounds__(256) agg2_kernel(const float4* __restrict__ b2,
                                                   float4* __restrict__ out4) {
    int node = blockIdx.x * 8 + (threadIdx.x >> 5);
    if (node >= NN) return;
    int lane = threadIdx.x & 31;
    int q = lane & 3, sub = lane >> 2;
    unsigned start = g_rowstart[node];
    unsigned cnt = g_deg[node];
    float4 acc = make_float4(0.f, 0.f, 0.f, 0.f);
    for (unsigned base = 0; base < cnt; base += 32) {
        unsigned n = cnt - base;
        if (n > 32u) n = 32u;
        int id = __ldg(&g_csr[start + base + (lane < n ? lane : n - 1)]);
#pragma unroll 2
        for (unsigned j = 0; j < n; j += 8) {
            unsigned jj = j + sub;
            int rr = __shfl_sync(0xffffffffu, id, jj < n ? jj : n - 1);
            if (jj < n) {
                uint2 u = __ldg((const uint2*)&g_h2s16[rr * 8 + 2 * q]);
                float2 f0 = __half22float2(*(__half2*)&u.x);
                float2 f1 = __half22float2(*(__half2*)&u.y);
                acc.x += f0.x; acc.y += f0.y; acc.z += f1.x; acc.w += f1.y;
            }
        }
    }
#pragma unroll
    for (int d = 4; d < 32; d <<= 1) {
        acc.x += __shfl_xor_sync(0xffffffffu, acc.x, d);
        acc.y += __shfl_xor_sync(0xffffffffu, acc.y, d);
        acc.z += __shfl_xor_sync(0xffffffffu, acc.z, d);
        acc.w += __shfl_xor_sync(0xffffffffu, acc.w, d);
    }
    if (lane == 0) g_deg[node] = 0u;             // reset for next replay
    if (node == 0 && lane == 1) g_total = 0u;    // reset scan base
    if (sub == 0) {
        uint2 u = __ldg((const uint2*)&g_h2s16[node * 8 + 2 * q]);
        float2 f0 = __half22float2(*(__half2*)&u.x);
        float2 f1 = __half22float2(*(__half2*)&u.y);
        float dv = __ldg(&g_dinv[node]);
        float4 bv = __ldg(&b2[q]);
        out4[node * 4 + q] =
            make_float4(fmaf(acc.x + f0.x, dv, bv.x), fmaf(acc.y + f0.y, dv, bv.y),
                        fmaf(acc.z + f1.x, dv, bv.z), fmaf(acc.w + f1.y, dv, bv.w));
    }
}

// ---------------- launch ----------------
extern "C" void kernel_launch(void* const* d_in, const int* in_sizes, int n_in,
                              void* d_out, int out_size) {
    const float* x = (const float*)d_in[0];
    const int* e32 = (const int*)d_in[1];
    const float* W1 = (const float*)d_in[2];
    const float* b1 = (const float*)d_in[3];
    const float* W2 = (const float*)d_in[4];
    const float* b2 = (const float*)d_in[5];
    int E = in_sizes[1] / 2;
    if (E > EMAX) E = EMAX;

    deg_count_kernel<<<(E + 255) / 256, 256>>>(e32, E);
    scan_fused_kernel<<<NBLK, 256>>>();
    csr_fill_kernel<<<(E + 255) / 256, 256>>>(e32, E);
    mm1_kernel<<<(NN * 2 + 255) / 256, 256>>>((const float4*)x, W1);
    agg1_kernel<<<(NN + 7) / 8, 256>>>();
    mm2_kernel<<<(NN * 2 + 255) / 256, 256>>>(W2, b1);
    agg2_kernel<<<(NN + 7) / 8, 256>>>((const float4*)b2, (float4*)d_out);
}